// round 1
// baseline (speedup 1.0000x reference)
#include <cuda_runtime.h>

#define NUM_STATES 20
#define BS 256
#define K_IN 1024
#define N_OUT 1024
#define CHUNK 8            // rows per block
#define NTILE 128          // output columns per block (= threads per block)
#define MAX_CHUNKS 5       // supports up to 40 samples per state (12.8 expected, ~8 sigma safe)
#define ROWS_CAP (CHUNK * MAX_CHUNKS)

// Scratch (no allocations allowed in kernel_launch)
__device__ int g_counts[NUM_STATES];
__device__ int g_rows[NUM_STATES * ROWS_CAP];

// ---------------------------------------------------------------------------
// Phase 1: bucket sample indices by state. One small block; rebuilt every
// launch (graph-replay safe). Row order within a bucket may vary run-to-run,
// but each row's output is an independent fixed-order k-sum -> deterministic.
// ---------------------------------------------------------------------------
__global__ void build_groups_kernel(const int* __restrict__ state) {
    __shared__ int cnt[NUM_STATES];
    int t = threadIdx.x;
    if (t < NUM_STATES) cnt[t] = 0;
    __syncthreads();
    if (t < BS) {
        int s = state[t];
        int p = atomicAdd(&cnt[s], 1);
        if (p < ROWS_CAP) g_rows[s * ROWS_CAP + p] = t;
    }
    __syncthreads();
    if (t < NUM_STATES) g_counts[t] = cnt[t];
}

// ---------------------------------------------------------------------------
// Phase 2 inner loop: NR accumulator rows held in registers (compile-time NR
// so acc[] never spills). Per 8 k's: 16 LDG.32 (kernel+mask, coalesced along
// n), 8 FMUL (w = kernel*mask), 2*NR broadcast LDS.128 of x, 8*NR FFMA.
// ---------------------------------------------------------------------------
template <int NR>
__device__ __forceinline__ void compute_tile(
    const float* __restrict__ kc,       // kernel + col
    const float* __restrict__ mc,       // masks + s*K*N + col
    const float (*__restrict__ xs)[K_IN],
    float* __restrict__ acc)
{
#pragma unroll
    for (int r = 0; r < NR; r++) acc[r] = 0.0f;

    for (int k = 0; k < K_IN; k += 8) {
        float w[8];
#pragma unroll
        for (int kk = 0; kk < 8; kk++) {
            size_t off = (size_t)(k + kk) * N_OUT;
            w[kk] = kc[off] * mc[off];
        }
#pragma unroll
        for (int r = 0; r < NR; r++) {
            float4 a = *(const float4*)&xs[r][k];
            float4 b = *(const float4*)&xs[r][k + 4];
            float t = acc[r];
            t = fmaf(a.x, w[0], t);
            t = fmaf(a.y, w[1], t);
            t = fmaf(a.z, w[2], t);
            t = fmaf(a.w, w[3], t);
            t = fmaf(b.x, w[4], t);
            t = fmaf(b.y, w[5], t);
            t = fmaf(b.z, w[6], t);
            t = fmaf(b.w, w[7], t);
            acc[r] = t;
        }
    }
}

// ---------------------------------------------------------------------------
// Phase 2: block = (row-chunk, n-tile, state). Chunk is the fastest grid dim
// so chunks sharing a mask tile are co-resident -> second read hits L2.
// ---------------------------------------------------------------------------
__global__ __launch_bounds__(NTILE) void masked_dense_kernel(
    const float* __restrict__ x,
    const float* __restrict__ kernel,
    const float* __restrict__ masks,
    float* __restrict__ out)
{
    int s  = blockIdx.z;
    int c  = g_counts[s];
    int r0 = blockIdx.x * CHUNK;
    if (r0 >= c) return;                 // empty chunk slot
    int nr = min(CHUNK, c - r0);

    __shared__ float xs[CHUNK][K_IN];    // 32 KB
    __shared__ int   rid_sm[CHUNK];

    int tid = threadIdx.x;

    // Stage x rows into smem: 16 threads per row; zero-fill padded rows.
    int r   = tid >> 4;                  // 0..7
    int sub = tid & 15;                  // 0..15
    int row = (r < nr) ? g_rows[s * ROWS_CAP + r0 + r] : -1;
    if (sub == 0) rid_sm[r] = row;
    {
        float4* dst = (float4*)xs[r];
        if (row >= 0) {
            const float4* src = (const float4*)(x + (size_t)row * K_IN);
#pragma unroll
            for (int i = sub; i < K_IN / 4; i += 16) dst[i] = src[i];
        } else {
            float4 z = make_float4(0.f, 0.f, 0.f, 0.f);
#pragma unroll
            for (int i = sub; i < K_IN / 4; i += 16) dst[i] = z;
        }
    }
    __syncthreads();

    int col = blockIdx.y * NTILE + tid;
    const float* kc = kernel + col;
    const float* mc = masks + (size_t)s * K_IN * N_OUT + col;

    float acc[CHUNK] = {};
    if (nr > 4) compute_tile<8>(kc, mc, xs, acc);
    else        compute_tile<4>(kc, mc, xs, acc);

#pragma unroll
    for (int rr = 0; rr < CHUNK; rr++) {
        if (rr < nr) {
            float v = acc[rr];
            out[(size_t)rid_sm[rr] * N_OUT + col] = v > 0.0f ? v : 0.0f;
        }
    }
}

// ---------------------------------------------------------------------------
// kernel_launch: inputs per metadata order: x(f32), state(i32), kernel(f32),
// masks(f32). Output f32 [256,1024]. Graph-capturable: kernel launches only.
// ---------------------------------------------------------------------------
extern "C" void kernel_launch(void* const* d_in, const int* in_sizes, int n_in,
                              void* d_out, int out_size) {
    const float* x      = (const float*)d_in[0];
    const int*   state  = (const int*)  d_in[1];
    const float* kernel = (const float*)d_in[2];
    const float* masks  = (const float*)d_in[3];
    float*       out    = (float*)d_out;

    build_groups_kernel<<<1, BS>>>(state);

    dim3 grid(MAX_CHUNKS, N_OUT / NTILE, NUM_STATES);
    masked_dense_kernel<<<grid, NTILE>>>(x, kernel, masks, out);
}

// round 2
// speedup vs baseline: 1.3379x; 1.3379x over previous
#include <cuda_runtime.h>

#define NUM_STATES 20
#define BS 256
#define K_IN 1024
#define N_OUT 1024
#define CHUNK 8            // rows per block
#define NTILE 128          // output columns per block (= threads per block)
#define MAX_CHUNKS 5       // supports up to 40 samples per state
#define ROWS_CAP (CHUNK * MAX_CHUNKS)
#define KSPLIT 4
#define KSLICE (K_IN / KSPLIT)   // 256

// Scratch (no allocations allowed anywhere)
__device__ int   g_counts[NUM_STATES];
__device__ int   g_rows[NUM_STATES * ROWS_CAP];
__device__ float g_partial[KSPLIT][BS][N_OUT];   // 4 MB static scratch

// ---------------------------------------------------------------------------
// Phase 1: bucket sample indices by state. Row order within a bucket may vary
// run-to-run, but each row's partial is an independent fixed-order k-sum ->
// deterministic output.
// ---------------------------------------------------------------------------
__global__ void build_groups_kernel(const int* __restrict__ state) {
    __shared__ int cnt[NUM_STATES];
    int t = threadIdx.x;
    if (t < NUM_STATES) cnt[t] = 0;
    __syncthreads();
    if (t < BS) {
        int s = state[t];
        int p = atomicAdd(&cnt[s], 1);
        if (p < ROWS_CAP) g_rows[s * ROWS_CAP + p] = t;
    }
    __syncthreads();
    if (t < NUM_STATES) g_counts[t] = cnt[t];
}

// ---------------------------------------------------------------------------
// Phase 2: block = (row-chunk, n-tile, state*KSPLIT+ks). Computes a partial
// dot product over a K/4 slice. 8 register accumulator rows; padded rows are
// zero-filled in smem so no per-row branching in the hot loop.
// Per 8 k's / thread: 16 LDG.32 (kernel+mask, coalesced), 8 FMUL,
// 16 broadcast LDS.128 of x, 64 FFMA.
// ---------------------------------------------------------------------------
__global__ __launch_bounds__(NTILE, 8) void masked_dense_partial(
    const float* __restrict__ x,
    const float* __restrict__ kernel,
    const float* __restrict__ masks)
{
    int z  = blockIdx.z;
    int s  = z >> 2;                  // state
    int ks = z & (KSPLIT - 1);        // k-slice index
    int c  = g_counts[s];
    int r0 = blockIdx.x * CHUNK;
    if (r0 >= c) return;              // empty chunk slot
    int nr = min(CHUNK, c - r0);

    __shared__ float xs[CHUNK][KSLICE];   // 8 KB
    __shared__ int   rid_sm[CHUNK];

    int tid = threadIdx.x;
    int k0  = ks * KSLICE;

    // Stage x row slices into smem: 16 threads per row; zero-fill padded rows.
    {
        int r   = tid >> 4;               // 0..7
        int sub = tid & 15;               // 0..15
        int row = (r < nr) ? g_rows[s * ROWS_CAP + r0 + r] : -1;
        if (sub == 0) rid_sm[r] = row;
        float4* dst = (float4*)xs[r];
        if (row >= 0) {
            const float4* src = (const float4*)(x + (size_t)row * K_IN + k0);
#pragma unroll
            for (int i = sub; i < KSLICE / 4; i += 16) dst[i] = src[i];
        } else {
            float4 zf = make_float4(0.f, 0.f, 0.f, 0.f);
#pragma unroll
            for (int i = sub; i < KSLICE / 4; i += 16) dst[i] = zf;
        }
    }
    __syncthreads();

    int col = blockIdx.y * NTILE + tid;
    const float* kc = kernel + (size_t)k0 * N_OUT + col;
    const float* mc = masks + ((size_t)s * K_IN + k0) * N_OUT + col;

    float acc[CHUNK];
#pragma unroll
    for (int r = 0; r < CHUNK; r++) acc[r] = 0.0f;

    for (int k = 0; k < KSLICE; k += 8) {
        float w[8];
#pragma unroll
        for (int kk = 0; kk < 8; kk++) {
            size_t off = (size_t)(k + kk) * N_OUT;
            w[kk] = kc[off] * mc[off];
        }
#pragma unroll
        for (int r = 0; r < CHUNK; r++) {
            float4 a = *(const float4*)&xs[r][k];
            float4 b = *(const float4*)&xs[r][k + 4];
            float t = acc[r];
            t = fmaf(a.x, w[0], t);
            t = fmaf(a.y, w[1], t);
            t = fmaf(a.z, w[2], t);
            t = fmaf(a.w, w[3], t);
            t = fmaf(b.x, w[4], t);
            t = fmaf(b.y, w[5], t);
            t = fmaf(b.z, w[6], t);
            t = fmaf(b.w, w[7], t);
            acc[r] = t;
        }
    }

#pragma unroll
    for (int rr = 0; rr < CHUNK; rr++) {
        if (rr < nr) {
            g_partial[ks][rid_sm[rr]][col] = acc[rr];
        }
    }
}

// ---------------------------------------------------------------------------
// Phase 3: deterministic fixed-order reduction over KSPLIT partials + relu.
// float4 per thread: 64K threads, ~9 MB traffic, ~2us.
// ---------------------------------------------------------------------------
__global__ void reduce_relu_kernel(float* __restrict__ out) {
    int i = blockIdx.x * blockDim.x + threadIdx.x;   // over BS*N_OUT/4
    const float4* p0 = (const float4*)&g_partial[0][0][0];
    const float4* p1 = (const float4*)&g_partial[1][0][0];
    const float4* p2 = (const float4*)&g_partial[2][0][0];
    const float4* p3 = (const float4*)&g_partial[3][0][0];
    float4 a = p0[i], b = p1[i], c = p2[i], d = p3[i];
    float4 r;
    r.x = fmaxf(a.x + b.x + c.x + d.x, 0.f);
    r.y = fmaxf(a.y + b.y + c.y + d.y, 0.f);
    r.z = fmaxf(a.z + b.z + c.z + d.z, 0.f);
    r.w = fmaxf(a.w + b.w + c.w + d.w, 0.f);
    ((float4*)out)[i] = r;
}

// ---------------------------------------------------------------------------
// kernel_launch: inputs per metadata order: x(f32), state(i32), kernel(f32),
// masks(f32). Output f32 [256,1024]. Graph-capturable: kernel launches only.
// ---------------------------------------------------------------------------
extern "C" void kernel_launch(void* const* d_in, const int* in_sizes, int n_in,
                              void* d_out, int out_size) {
    const float* x      = (const float*)d_in[0];
    const int*   state  = (const int*)  d_in[1];
    const float* kernel = (const float*)d_in[2];
    const float* masks  = (const float*)d_in[3];
    float*       out    = (float*)d_out;

    build_groups_kernel<<<1, BS>>>(state);

    dim3 grid(MAX_CHUNKS, N_OUT / NTILE, NUM_STATES * KSPLIT);
    masked_dense_partial<<<grid, NTILE>>>(x, kernel, masks);

    int nvec = BS * N_OUT / 4;   // 65536
    reduce_relu_kernel<<<nvec / 256, 256>>>(out);
}

// round 3
// speedup vs baseline: 2.0993x; 1.5691x over previous
#include <cuda_runtime.h>

#define NUM_STATES 20
#define BS 256
#define K_IN 1024
#define N_OUT 1024
#define CHUNK 8                   // rows per block
#define THREADS 128
#define COLS_PER_THREAD 4
#define COLTILE (THREADS * COLS_PER_THREAD)   // 512
#define MAX_CHUNKS 5              // up to 40 samples per state (mean 12.8, sd 3.5)
#define KSPLIT 8
#define KSLICE (K_IN / KSPLIT)    // 128
#define NV (N_OUT / 4)            // float4 stride of a weight row

// Static scratch (no allocations allowed anywhere)
__device__ float g_partial[KSPLIT][BS][N_OUT];   // 8 MB

// ---------------------------------------------------------------------------
// Main kernel: block = (row-chunk, col-tile, state*KSPLIT + ks).
// Grouping is recomputed in-block (deterministic ballot+prefix over state[]),
// so there is no separate bucketing kernel and no cross-launch dependency.
// Each thread owns 4 consecutive output columns -> LDG.128 on kernel & mask.
// ---------------------------------------------------------------------------
__global__ __launch_bounds__(THREADS, 4) void masked_dense_partial(
    const float* __restrict__ x,
    const int*   __restrict__ state,
    const float* __restrict__ kernel,
    const float* __restrict__ masks)
{
    const int z  = blockIdx.z;
    const int s  = z / KSPLIT;
    const int ks = z % KSPLIT;
    const int r0 = blockIdx.x * CHUNK;

    const int tid  = threadIdx.x;
    const int lane = tid & 31;
    const int warp = tid >> 5;

    __shared__ int segcnt[8];
    __shared__ int rows_sm[CHUNK];
    __shared__ float xs[CHUNK][KSLICE];   // 4 KB

    // ---- deterministic in-block grouping: ordered list of rows with state==s
    const int pos0 = tid;          // 0..127
    const int pos1 = tid + 128;    // 128..255
    const int s0 = state[pos0];
    const int s1 = state[pos1];
    const unsigned b0 = __ballot_sync(0xffffffffu, s0 == s);
    const unsigned b1 = __ballot_sync(0xffffffffu, s1 == s);
    if (lane == 0) { segcnt[warp] = __popc(b0); segcnt[warp + 4] = __popc(b1); }
    if (tid < CHUNK) rows_sm[tid] = -1;
    __syncthreads();

    int pre[8];
    int c = 0;
#pragma unroll
    for (int i = 0; i < 8; i++) { pre[i] = c; c += segcnt[i]; }
    if (r0 >= c) return;                       // empty chunk slot
    const int nr = min(CHUNK, c - r0);

    const unsigned lmask = (1u << lane) - 1u;
    const int rank0 = pre[warp]     + __popc(b0 & lmask);
    const int rank1 = pre[warp + 4] + __popc(b1 & lmask);
    if (s0 == s && rank0 >= r0 && rank0 < r0 + CHUNK) rows_sm[rank0 - r0] = pos0;
    if (s1 == s && rank1 >= r0 && rank1 < r0 + CHUNK) rows_sm[rank1 - r0] = pos1;
    __syncthreads();

    // ---- stage x row slices (k0..k0+KSLICE) into smem; zero-fill pad rows
    const int k0 = ks * KSLICE;
    {
        const int r   = tid >> 4;              // 0..7
        const int sub = tid & 15;              // 0..15
        const int row = rows_sm[r];
        float4* dst = (float4*)xs[r];
        if (row >= 0) {
            const float4* src = (const float4*)(x + (size_t)row * K_IN + k0);
#pragma unroll
            for (int i = sub; i < KSLICE / 4; i += 16) dst[i] = src[i];
        } else {
            const float4 zf = make_float4(0.f, 0.f, 0.f, 0.f);
#pragma unroll
            for (int i = sub; i < KSLICE / 4; i += 16) dst[i] = zf;
        }
    }
    __syncthreads();

    // ---- main loop: per 4 k's: 8 LDG.128 (kernel+mask), 16 FMUL,
    //      8 broadcast LDS.128 of x, 128 FFMA.
    const int col0 = blockIdx.y * COLTILE + tid * COLS_PER_THREAD;
    const float4* kc = (const float4*)(kernel + (size_t)k0 * N_OUT + col0);
    const float4* mc = (const float4*)(masks + ((size_t)s * K_IN + k0) * N_OUT + col0);

    float4 acc[CHUNK];
#pragma unroll
    for (int r = 0; r < CHUNK; r++) acc[r] = make_float4(0.f, 0.f, 0.f, 0.f);

    for (int k = 0; k < KSLICE; k += 4) {
        float4 k0v = kc[(size_t)(k + 0) * NV];
        float4 k1v = kc[(size_t)(k + 1) * NV];
        float4 k2v = kc[(size_t)(k + 2) * NV];
        float4 k3v = kc[(size_t)(k + 3) * NV];
        float4 m0v = mc[(size_t)(k + 0) * NV];
        float4 m1v = mc[(size_t)(k + 1) * NV];
        float4 m2v = mc[(size_t)(k + 2) * NV];
        float4 m3v = mc[(size_t)(k + 3) * NV];

        float4 w0, w1, w2, w3;
        w0.x = k0v.x * m0v.x; w0.y = k0v.y * m0v.y; w0.z = k0v.z * m0v.z; w0.w = k0v.w * m0v.w;
        w1.x = k1v.x * m1v.x; w1.y = k1v.y * m1v.y; w1.z = k1v.z * m1v.z; w1.w = k1v.w * m1v.w;
        w2.x = k2v.x * m2v.x; w2.y = k2v.y * m2v.y; w2.z = k2v.z * m2v.z; w2.w = k2v.w * m2v.w;
        w3.x = k3v.x * m3v.x; w3.y = k3v.y * m3v.y; w3.z = k3v.z * m3v.z; w3.w = k3v.w * m3v.w;

#pragma unroll
        for (int r = 0; r < CHUNK; r++) {
            const float4 xv = *(const float4*)&xs[r][k];
            float4 a = acc[r];
            a.x = fmaf(xv.x, w0.x, a.x); a.y = fmaf(xv.x, w0.y, a.y);
            a.z = fmaf(xv.x, w0.z, a.z); a.w = fmaf(xv.x, w0.w, a.w);
            a.x = fmaf(xv.y, w1.x, a.x); a.y = fmaf(xv.y, w1.y, a.y);
            a.z = fmaf(xv.y, w1.z, a.z); a.w = fmaf(xv.y, w1.w, a.w);
            a.x = fmaf(xv.z, w2.x, a.x); a.y = fmaf(xv.z, w2.y, a.y);
            a.z = fmaf(xv.z, w2.z, a.z); a.w = fmaf(xv.z, w2.w, a.w);
            a.x = fmaf(xv.w, w3.x, a.x); a.y = fmaf(xv.w, w3.y, a.y);
            a.z = fmaf(xv.w, w3.z, a.z); a.w = fmaf(xv.w, w3.w, a.w);
            acc[r] = a;
        }
    }

#pragma unroll
    for (int rr = 0; rr < CHUNK; rr++) {
        const int rid = rows_sm[rr];
        if (rr < nr && rid >= 0) {
            *(float4*)&g_partial[ks][rid][col0] = acc[rr];
        }
    }
}

// ---------------------------------------------------------------------------
// Deterministic fixed-order reduction over KSPLIT partials + relu.
// ---------------------------------------------------------------------------
__global__ void reduce_relu_kernel(float* __restrict__ out) {
    const int i = blockIdx.x * blockDim.x + threadIdx.x;   // over BS*N_OUT/4
    float4 a = ((const float4*)&g_partial[0][0][0])[i];
#pragma unroll
    for (int p = 1; p < KSPLIT; p++) {
        const float4 b = ((const float4*)&g_partial[p][0][0])[i];
        a.x += b.x; a.y += b.y; a.z += b.z; a.w += b.w;
    }
    float4 r;
    r.x = fmaxf(a.x, 0.f);
    r.y = fmaxf(a.y, 0.f);
    r.z = fmaxf(a.z, 0.f);
    r.w = fmaxf(a.w, 0.f);
    ((float4*)out)[i] = r;
}

// ---------------------------------------------------------------------------
// kernel_launch: inputs per metadata order: x(f32), state(i32), kernel(f32),
// masks(f32). Output f32 [256,1024]. Graph-capturable: kernel launches only.
// ---------------------------------------------------------------------------
extern "C" void kernel_launch(void* const* d_in, const int* in_sizes, int n_in,
                              void* d_out, int out_size) {
    const float* x      = (const float*)d_in[0];
    const int*   state  = (const int*)  d_in[1];
    const float* kernel = (const float*)d_in[2];
    const float* masks  = (const float*)d_in[3];
    float*       out    = (float*)d_out;

    dim3 grid(MAX_CHUNKS, N_OUT / COLTILE, NUM_STATES * KSPLIT);
    masked_dense_partial<<<grid, THREADS>>>(x, state, kernel, masks);

    const int nvec = BS * N_OUT / 4;   // 65536
    reduce_relu_kernel<<<nvec / 256, 256>>>(out);
}